// round 2
// baseline (speedup 1.0000x reference)
#include <cuda_runtime.h>
#include <math.h>
#include <stdint.h>

// Problem dims
#define BB 32
#define TT 512
#define II 128
#define HH 512
#define OO 128

// ---------------- device scratch (no allocs allowed) ----------------
__device__ float    g_pre [TT * HH * BB];   // [T][H][B] (reused pre0/pre1)
__device__ float    g_traj[TT * HH * BB];   // [T][H][B] (h1, then reused as h2)
__device__ float    g_tmp [TT * OO * BB];   // [T][O][B] (fc pre-transpose)
__device__ float    g_hping[4 * HH * BB];   // 2 ping-pong pairs (layer0, layer1)
__device__ unsigned g_counters[1024];       // per-step barrier counters (512 per layer)

// ---------------- init: zero counters + h0 buffers each replay ----------------
__global__ void init_kernel(unsigned* counters, float* hping) {
    int i = blockIdx.x * blockDim.x + threadIdx.x;
    int stride = gridDim.x * blockDim.x;
    for (int e = i; e < 1024; e += stride) counters[e] = 0u;
    for (int e = i; e < 4 * HH * BB; e += stride) hping[e] = 0.0f;
}

// ---------------- fp32 GEMM: C[t][j][b] = bias(j) + sum_k A(t,k,b)*W[j][k] ----------------
// grid: (N/128, T), block: 128 threads. Tile 128j x 32b, microtile 8x4.
__global__ void __launch_bounds__(128)
gemm_pre_kernel(const float* __restrict__ A, const float* __restrict__ W,
                const float* __restrict__ bias1, const float* __restrict__ bias2,
                float* __restrict__ C,
                int K, long sAt, long sAk, long sAb, int N)
{
    __shared__ float Ws[32][132];  // [k][j] padded (128 j)
    __shared__ float As[32][36];   // [k][b] padded

    const int t   = blockIdx.y;
    const int j0  = blockIdx.x * 128;
    const int tid = threadIdx.x;
    const int jg  = tid & 15;      // 16 j-groups of 8
    const int bg  = tid >> 4;      // 8 b-groups of 4

    float acc[8][4];
#pragma unroll
    for (int a = 0; a < 8; a++)
#pragma unroll
        for (int b = 0; b < 4; b++) acc[a][b] = 0.0f;

    for (int kt = 0; kt < K; kt += 32) {
        __syncthreads();
        // stage W tile transposed: each thread loads one j-row's 32 k values
        {
            const float* wp = &W[(size_t)(j0 + tid) * K + kt];
#pragma unroll
            for (int i = 0; i < 32; i += 4) {
                float4 v = *(const float4*)(wp + i);
                Ws[i + 0][tid] = v.x;
                Ws[i + 1][tid] = v.y;
                Ws[i + 2][tid] = v.z;
                Ws[i + 3][tid] = v.w;
            }
        }
        // stage A tile: 32 k x 32 b
        if (sAb == 1) {   // b-contiguous (trajectory layout [t][k][b])
#pragma unroll
            for (int i = 0; i < 2; i++) {
                int f = tid + i * 128;
                int k = f >> 3, b4 = (f & 7) * 4;
                float4 v = *(const float4*)&A[(size_t)t * sAt + (size_t)(kt + k) * sAk + b4];
                *(float4*)&As[k][b4] = v;
            }
        } else {          // k-contiguous (inputs layout [b][t][i])
#pragma unroll
            for (int i = 0; i < 2; i++) {
                int f = tid + i * 128;
                int b = f >> 3, kq = (f & 7) * 4;
                float4 v = *(const float4*)&A[(size_t)b * sAb + (size_t)t * sAt + kt + kq];
                As[kq + 0][b] = v.x;
                As[kq + 1][b] = v.y;
                As[kq + 2][b] = v.z;
                As[kq + 3][b] = v.w;
            }
        }
        __syncthreads();
#pragma unroll
        for (int k = 0; k < 32; k++) {
            const float4 w0 = *(const float4*)&Ws[k][jg * 8];
            const float4 w1 = *(const float4*)&Ws[k][jg * 8 + 4];
            const float4 a  = *(const float4*)&As[k][bg * 4];
            acc[0][0] += w0.x * a.x; acc[0][1] += w0.x * a.y; acc[0][2] += w0.x * a.z; acc[0][3] += w0.x * a.w;
            acc[1][0] += w0.y * a.x; acc[1][1] += w0.y * a.y; acc[1][2] += w0.y * a.z; acc[1][3] += w0.y * a.w;
            acc[2][0] += w0.z * a.x; acc[2][1] += w0.z * a.y; acc[2][2] += w0.z * a.z; acc[2][3] += w0.z * a.w;
            acc[3][0] += w0.w * a.x; acc[3][1] += w0.w * a.y; acc[3][2] += w0.w * a.z; acc[3][3] += w0.w * a.w;
            acc[4][0] += w1.x * a.x; acc[4][1] += w1.x * a.y; acc[4][2] += w1.x * a.z; acc[4][3] += w1.x * a.w;
            acc[5][0] += w1.y * a.x; acc[5][1] += w1.y * a.y; acc[5][2] += w1.y * a.z; acc[5][3] += w1.y * a.w;
            acc[6][0] += w1.z * a.x; acc[6][1] += w1.z * a.y; acc[6][2] += w1.z * a.z; acc[6][3] += w1.z * a.w;
            acc[7][0] += w1.w * a.x; acc[7][1] += w1.w * a.y; acc[7][2] += w1.w * a.z; acc[7][3] += w1.w * a.w;
        }
    }

#pragma unroll
    for (int ji = 0; ji < 8; ji++) {
        int j = j0 + jg * 8 + ji;
        float bb = bias1 ? bias1[j] : 0.0f;
        if (bias2) bb += bias2[j];
        float4 o = make_float4(acc[ji][0] + bb, acc[ji][1] + bb, acc[ji][2] + bb, acc[ji][3] + bb);
        *(float4*)&C[(size_t)t * N * BB + (size_t)j * BB + bg * 4] = o;
    }
}

// ---------------- persistent recurrence layer ----------------
// grid: 128 CTAs (co-resident), block: 256 threads. CTA owns 4 hidden columns.
// h buffers [H][B]. Grid barrier per step: red.release + ld.acquire spin.
__global__ void __launch_bounds__(256)
rnn_layer_kernel(const float* __restrict__ pre, float* __restrict__ traj,
                 const float* __restrict__ W,
                 float* buf0, float* buf1, unsigned* counters)
{
    __shared__ float Wt[16][32][4];   // [kk][kseg][jj]  8KB
    __shared__ float ps[32][132];     // partials [kseg][out] padded  ~17KB

    const int tid  = threadIdx.x;
    const int j0   = blockIdx.x * 4;
    const int kseg = tid >> 3;        // 0..31 (16 k each)
    const int bg   = tid & 7;         // 0..7  (4 b each)

    // preload W slice: Wt[kk][ks][jj] = W[(j0+jj)*H + ks*16 + kk]
    for (int e = tid; e < 2048; e += 256) {
        int jj = e & 3;
        int ks = (e >> 2) & 31;
        int kk = e >> 7;
        Wt[kk][ks][jj] = W[(size_t)(j0 + jj) * HH + ks * 16 + kk];
    }
    __syncthreads();

    const int out_b  = tid >> 2;      // for tid<128: output this thread finalizes
    const int out_jj = tid & 3;

    for (int t = 0; t < TT; t++) {
        const float* hb = (t & 1) ? buf1 : buf0;
        float*       hn = (t & 1) ? buf0 : buf1;

        float preval = 0.0f;
        if (tid < 128)
            preval = pre[(size_t)t * (HH * BB) + (size_t)(j0 + out_jj) * BB + out_b];

        float acc[4][4];
#pragma unroll
        for (int a = 0; a < 4; a++)
#pragma unroll
            for (int b = 0; b < 4; b++) acc[a][b] = 0.0f;

        const float* hptr = hb + kseg * 16 * BB + bg * 4;
#pragma unroll
        for (int kk = 0; kk < 16; kk++) {
            const float4 w = *(const float4*)&Wt[kk][kseg][0];
            const float4 h = __ldcg((const float4*)(hptr + kk * BB));
            acc[0][0] += h.x * w.x; acc[0][1] += h.x * w.y; acc[0][2] += h.x * w.z; acc[0][3] += h.x * w.w;
            acc[1][0] += h.y * w.x; acc[1][1] += h.y * w.y; acc[1][2] += h.y * w.z; acc[1][3] += h.y * w.w;
            acc[2][0] += h.z * w.x; acc[2][1] += h.z * w.y; acc[2][2] += h.z * w.z; acc[2][3] += h.z * w.w;
            acc[3][0] += h.w * w.x; acc[3][1] += h.w * w.y; acc[3][2] += h.w * w.z; acc[3][3] += h.w * w.w;
        }

        // dump partials: out index o = b*4 + jj, b = bg*4+bi
#pragma unroll
        for (int bi = 0; bi < 4; bi++) {
            *(float4*)&ps[kseg][(bg * 4 + bi) * 4] =
                make_float4(acc[bi][0], acc[bi][1], acc[bi][2], acc[bi][3]);
        }
        __syncthreads();

        if (tid < 128) {
            float s0 = 0.f, s1 = 0.f, s2 = 0.f, s3 = 0.f;
#pragma unroll
            for (int ss = 0; ss < 32; ss += 4) {
                s0 += ps[ss + 0][tid];
                s1 += ps[ss + 1][tid];
                s2 += ps[ss + 2][tid];
                s3 += ps[ss + 3][tid];
            }
            const float val = tanhf(preval + (s0 + s1) + (s2 + s3));
            const int jdx = j0 + out_jj;
            hn[(size_t)jdx * BB + out_b] = val;
            traj[(size_t)t * (HH * BB) + (size_t)jdx * BB + out_b] = val;
        }
        __syncthreads();   // stores issued by all; also guards ps reuse

        if (tid == 0) {
            unsigned* cnt = &counters[t];
            asm volatile("red.release.gpu.global.add.u32 [%0], 1;" :: "l"(cnt) : "memory");
            unsigned v;
            do {
                asm volatile("ld.acquire.gpu.global.u32 %0, [%1];" : "=r"(v) : "l"(cnt) : "memory");
            } while (v < 128u);
        }
        __syncthreads();
    }
}

// ---------------- transpose: g_tmp [T][O][B] -> out [B][O][T] ----------------
__global__ void transpose_kernel(const float* __restrict__ tmp, float* __restrict__ out)
{
    __shared__ float s[32][33];
    const int t0 = blockIdx.x * 32;
    const int o  = blockIdx.y;
    const int tx = threadIdx.x;   // 32
    const int ty = threadIdx.y;   // 8
#pragma unroll
    for (int i = 0; i < 4; i++) {
        int tt = t0 + ty + i * 8;
        s[ty + i * 8][tx] = tmp[(size_t)tt * (OO * BB) + (size_t)o * BB + tx];
    }
    __syncthreads();
#pragma unroll
    for (int i = 0; i < 4; i++) {
        int b = ty + i * 8;
        out[(size_t)b * (OO * TT) + (size_t)o * TT + t0 + tx] = s[tx][b];
    }
}

// ---------------- launch ----------------
extern "C" void kernel_launch(void* const* d_in, const int* in_sizes, int n_in,
                              void* d_out, int out_size)
{
    const float* inputs = (const float*)d_in[0];
    const float* W_ih0  = (const float*)d_in[1];
    const float* W_hh0  = (const float*)d_in[2];
    const float* b_ih0  = (const float*)d_in[3];
    const float* b_hh0  = (const float*)d_in[4];
    const float* W_ih1  = (const float*)d_in[5];
    const float* W_hh1  = (const float*)d_in[6];
    const float* b_ih1  = (const float*)d_in[7];
    const float* b_hh1  = (const float*)d_in[8];
    const float* W_fc   = (const float*)d_in[9];
    const float* b_fc   = (const float*)d_in[10];

    float *pre, *traj, *tmp, *hping;
    unsigned* counters;
    cudaGetSymbolAddress((void**)&pre,      g_pre);
    cudaGetSymbolAddress((void**)&traj,     g_traj);
    cudaGetSymbolAddress((void**)&tmp,      g_tmp);
    cudaGetSymbolAddress((void**)&hping,    g_hping);
    cudaGetSymbolAddress((void**)&counters, g_counters);

    init_kernel<<<64, 256>>>(counters, hping);

    // pre0[t][j][b] = inputs[b][t][:] . W_ih0[j][:] + b_ih0[j] + b_hh0[j]
    gemm_pre_kernel<<<dim3(4, TT), 128>>>(inputs, W_ih0, b_ih0, b_hh0, pre,
                                          II, (long)II, 1L, (long)TT * II, HH);

    // layer 0 recurrence -> h1 trajectory
    rnn_layer_kernel<<<128, 256>>>(pre, traj, W_hh0,
                                   hping, hping + HH * BB, counters);

    // pre1[t][j][b] = h1[t][:][b] . W_ih1[j][:] + b_ih1[j] + b_hh1[j]
    gemm_pre_kernel<<<dim3(4, TT), 128>>>(traj, W_ih1, b_ih1, b_hh1, pre,
                                          HH, (long)HH * BB, (long)BB, 1L, HH);

    // layer 1 recurrence -> h2 trajectory (reuses g_traj)
    rnn_layer_kernel<<<128, 256>>>(pre, traj, W_hh1,
                                   hping + 2 * HH * BB, hping + 3 * HH * BB,
                                   counters + 512);

    // fc: tmp[t][o][b] = h2[t][:][b] . W_fc[o][:] + b_fc[o]
    gemm_pre_kernel<<<dim3(1, TT), 128>>>(traj, W_fc, b_fc, nullptr, tmp,
                                          HH, (long)HH * BB, (long)BB, 1L, OO);

    // out[b][o][t] = tmp[t][o][b]
    transpose_kernel<<<dim3(16, OO), dim3(32, 8)>>>(tmp, (float*)d_out);
}

// round 3
// speedup vs baseline: 1.0022x; 1.0022x over previous
#include <cuda_runtime.h>
#include <math.h>
#include <stdint.h>

// Problem dims
#define BB 32
#define TT 512
#define II 128
#define HH 512
#define OO 128

// ---------------- device scratch (no allocs allowed) ----------------
__device__ float    g_pre [TT * HH * BB];   // [T][H][B] (reused pre0/pre1)
__device__ float    g_traj[TT * HH * BB];   // [T][H][B] (h1, then reused as h2)
__device__ float    g_tmp [TT * OO * BB];   // [T][O][B] (fc pre-transpose)
__device__ float    g_hping[4 * HH * BB];   // 2 ping-pong pairs (layer0, layer1)
__device__ unsigned g_counters[1024];       // per-step barrier counters (512 per layer)

// ---------------- init: zero counters + h0 buffers each replay ----------------
__global__ void init_kernel(unsigned* counters, float* hping) {
    int i = blockIdx.x * blockDim.x + threadIdx.x;
    int stride = gridDim.x * blockDim.x;
    for (int e = i; e < 1024; e += stride) counters[e] = 0u;
    for (int e = i; e < 4 * HH * BB; e += stride) hping[e] = 0.0f;
}

// ---------------- fp32 GEMM: C[t][j][b] = bias(j) + sum_k A(t,k,b)*W[j][k] ----------------
// grid: (N/128, T), block: 128 threads. Tile 128j x 32b, microtile 8x4.
__global__ void __launch_bounds__(128)
gemm_pre_kernel(const float* __restrict__ A, const float* __restrict__ W,
                const float* __restrict__ bias1, const float* __restrict__ bias2,
                float* __restrict__ C,
                int K, long sAt, long sAk, long sAb, int N)
{
    __shared__ float Ws[32][132];  // [k][j] padded (128 j)
    __shared__ float As[32][36];   // [k][b] padded

    const int t   = blockIdx.y;
    const int j0  = blockIdx.x * 128;
    const int tid = threadIdx.x;
    const int jg  = tid & 15;      // 16 j-groups of 8
    const int bg  = tid >> 4;      // 8 b-groups of 4

    float acc[8][4];
#pragma unroll
    for (int a = 0; a < 8; a++)
#pragma unroll
        for (int b = 0; b < 4; b++) acc[a][b] = 0.0f;

    for (int kt = 0; kt < K; kt += 32) {
        __syncthreads();
        // stage W tile transposed: each thread loads one j-row's 32 k values
        {
            const float* wp = &W[(size_t)(j0 + tid) * K + kt];
#pragma unroll
            for (int i = 0; i < 32; i += 4) {
                float4 v = *(const float4*)(wp + i);
                Ws[i + 0][tid] = v.x;
                Ws[i + 1][tid] = v.y;
                Ws[i + 2][tid] = v.z;
                Ws[i + 3][tid] = v.w;
            }
        }
        // stage A tile: 32 k x 32 b
        if (sAb == 1) {   // b-contiguous (trajectory layout [t][k][b])
#pragma unroll
            for (int i = 0; i < 2; i++) {
                int f = tid + i * 128;
                int k = f >> 3, b4 = (f & 7) * 4;
                float4 v = *(const float4*)&A[(size_t)t * sAt + (size_t)(kt + k) * sAk + b4];
                *(float4*)&As[k][b4] = v;
            }
        } else {          // k-contiguous (inputs layout [b][t][i])
#pragma unroll
            for (int i = 0; i < 2; i++) {
                int f = tid + i * 128;
                int b = f >> 3, kq = (f & 7) * 4;
                float4 v = *(const float4*)&A[(size_t)b * sAb + (size_t)t * sAt + kt + kq];
                As[kq + 0][b] = v.x;
                As[kq + 1][b] = v.y;
                As[kq + 2][b] = v.z;
                As[kq + 3][b] = v.w;
            }
        }
        __syncthreads();
#pragma unroll
        for (int k = 0; k < 32; k++) {
            const float4 w0 = *(const float4*)&Ws[k][jg * 8];
            const float4 w1 = *(const float4*)&Ws[k][jg * 8 + 4];
            const float4 a  = *(const float4*)&As[k][bg * 4];
            acc[0][0] += w0.x * a.x; acc[0][1] += w0.x * a.y; acc[0][2] += w0.x * a.z; acc[0][3] += w0.x * a.w;
            acc[1][0] += w0.y * a.x; acc[1][1] += w0.y * a.y; acc[1][2] += w0.y * a.z; acc[1][3] += w0.y * a.w;
            acc[2][0] += w0.z * a.x; acc[2][1] += w0.z * a.y; acc[2][2] += w0.z * a.z; acc[2][3] += w0.z * a.w;
            acc[3][0] += w0.w * a.x; acc[3][1] += w0.w * a.y; acc[3][2] += w0.w * a.z; acc[3][3] += w0.w * a.w;
            acc[4][0] += w1.x * a.x; acc[4][1] += w1.x * a.y; acc[4][2] += w1.x * a.z; acc[4][3] += w1.x * a.w;
            acc[5][0] += w1.y * a.x; acc[5][1] += w1.y * a.y; acc[5][2] += w1.y * a.z; acc[5][3] += w1.y * a.w;
            acc[6][0] += w1.z * a.x; acc[6][1] += w1.z * a.y; acc[6][2] += w1.z * a.z; acc[6][3] += w1.z * a.w;
            acc[7][0] += w1.w * a.x; acc[7][1] += w1.w * a.y; acc[7][2] += w1.w * a.z; acc[7][3] += w1.w * a.w;
        }
    }

#pragma unroll
    for (int ji = 0; ji < 8; ji++) {
        int j = j0 + jg * 8 + ji;
        float bb = bias1 ? bias1[j] : 0.0f;
        if (bias2) bb += bias2[j];
        float4 o = make_float4(acc[ji][0] + bb, acc[ji][1] + bb, acc[ji][2] + bb, acc[ji][3] + bb);
        *(float4*)&C[(size_t)t * N * BB + (size_t)j * BB + bg * 4] = o;
    }
}

// ---------------- persistent recurrence layer ----------------
// grid: 128 CTAs (co-resident), block: 256 threads. CTA owns 4 hidden columns.
// h buffers [H][B]. Grid barrier per step: red.release + ld.acquire spin.
__global__ void __launch_bounds__(256)
rnn_layer_kernel(const float* __restrict__ pre, float* __restrict__ traj,
                 const float* __restrict__ W,
                 float* buf0, float* buf1, unsigned* counters)
{
    __shared__ float Wt[16][32][4];   // [kk][kseg][jj]  8KB
    __shared__ float ps[32][132];     // partials [kseg][out] padded  ~17KB

    const int tid  = threadIdx.x;
    const int j0   = blockIdx.x * 4;
    const int kseg = tid >> 3;        // 0..31 (16 k each)
    const int bg   = tid & 7;         // 0..7  (4 b each)

    // preload W slice: Wt[kk][ks][jj] = W[(j0+jj)*H + ks*16 + kk]
    for (int e = tid; e < 2048; e += 256) {
        int jj = e & 3;
        int ks = (e >> 2) & 31;
        int kk = e >> 7;
        Wt[kk][ks][jj] = W[(size_t)(j0 + jj) * HH + ks * 16 + kk];
    }
    __syncthreads();

    const int out_b  = tid >> 2;      // for tid<128: output this thread finalizes
    const int out_jj = tid & 3;

    for (int t = 0; t < TT; t++) {
        const float* hb = (t & 1) ? buf1 : buf0;
        float*       hn = (t & 1) ? buf0 : buf1;

        float preval = 0.0f;
        if (tid < 128)
            preval = pre[(size_t)t * (HH * BB) + (size_t)(j0 + out_jj) * BB + out_b];

        float acc[4][4];
#pragma unroll
        for (int a = 0; a < 4; a++)
#pragma unroll
            for (int b = 0; b < 4; b++) acc[a][b] = 0.0f;

        const float* hptr = hb + kseg * 16 * BB + bg * 4;
#pragma unroll
        for (int kk = 0; kk < 16; kk++) {
            const float4 w = *(const float4*)&Wt[kk][kseg][0];
            const float4 h = __ldcg((const float4*)(hptr + kk * BB));
            acc[0][0] += h.x * w.x; acc[0][1] += h.x * w.y; acc[0][2] += h.x * w.z; acc[0][3] += h.x * w.w;
            acc[1][0] += h.y * w.x; acc[1][1] += h.y * w.y; acc[1][2] += h.y * w.z; acc[1][3] += h.y * w.w;
            acc[2][0] += h.z * w.x; acc[2][1] += h.z * w.y; acc[2][2] += h.z * w.z; acc[2][3] += h.z * w.w;
            acc[3][0] += h.w * w.x; acc[3][1] += h.w * w.y; acc[3][2] += h.w * w.z; acc[3][3] += h.w * w.w;
        }

        // dump partials: out index o = b*4 + jj, b = bg*4+bi
#pragma unroll
        for (int bi = 0; bi < 4; bi++) {
            *(float4*)&ps[kseg][(bg * 4 + bi) * 4] =
                make_float4(acc[bi][0], acc[bi][1], acc[bi][2], acc[bi][3]);
        }
        __syncthreads();

        if (tid < 128) {
            float s0 = 0.f, s1 = 0.f, s2 = 0.f, s3 = 0.f;
#pragma unroll
            for (int ss = 0; ss < 32; ss += 4) {
                s0 += ps[ss + 0][tid];
                s1 += ps[ss + 1][tid];
                s2 += ps[ss + 2][tid];
                s3 += ps[ss + 3][tid];
            }
            const float val = tanhf(preval + (s0 + s1) + (s2 + s3));
            const int jdx = j0 + out_jj;
            hn[(size_t)jdx * BB + out_b] = val;
            traj[(size_t)t * (HH * BB) + (size_t)jdx * BB + out_b] = val;
        }
        __syncthreads();   // stores issued by all; also guards ps reuse

        if (tid == 0) {
            unsigned* cnt = &counters[t];
            asm volatile("red.release.gpu.global.add.u32 [%0], 1;" :: "l"(cnt) : "memory");
            unsigned v;
            do {
                asm volatile("ld.acquire.gpu.global.u32 %0, [%1];" : "=r"(v) : "l"(cnt) : "memory");
            } while (v < 128u);
        }
        __syncthreads();
    }
}

// ---------------- transpose: g_tmp [T][O][B] -> out [B][O][T] ----------------
__global__ void transpose_kernel(const float* __restrict__ tmp, float* __restrict__ out)
{
    __shared__ float s[32][33];
    const int t0 = blockIdx.x * 32;
    const int o  = blockIdx.y;
    const int tx = threadIdx.x;   // 32
    const int ty = threadIdx.y;   // 8
#pragma unroll
    for (int i = 0; i < 4; i++) {
        int tt = t0 + ty + i * 8;
        s[ty + i * 8][tx] = tmp[(size_t)tt * (OO * BB) + (size_t)o * BB + tx];
    }
    __syncthreads();
#pragma unroll
    for (int i = 0; i < 4; i++) {
        int b = ty + i * 8;
        out[(size_t)b * (OO * TT) + (size_t)o * TT + t0 + tx] = s[tx][b];
    }
}

// ---------------- launch ----------------
extern "C" void kernel_launch(void* const* d_in, const int* in_sizes, int n_in,
                              void* d_out, int out_size)
{
    const float* inputs = (const float*)d_in[0];
    const float* W_ih0  = (const float*)d_in[1];
    const float* W_hh0  = (const float*)d_in[2];
    const float* b_ih0  = (const float*)d_in[3];
    const float* b_hh0  = (const float*)d_in[4];
    const float* W_ih1  = (const float*)d_in[5];
    const float* W_hh1  = (const float*)d_in[6];
    const float* b_ih1  = (const float*)d_in[7];
    const float* b_hh1  = (const float*)d_in[8];
    const float* W_fc   = (const float*)d_in[9];
    const float* b_fc   = (const float*)d_in[10];

    float *pre, *traj, *tmp, *hping;
    unsigned* counters;
    cudaGetSymbolAddress((void**)&pre,      g_pre);
    cudaGetSymbolAddress((void**)&traj,     g_traj);
    cudaGetSymbolAddress((void**)&tmp,      g_tmp);
    cudaGetSymbolAddress((void**)&hping,    g_hping);
    cudaGetSymbolAddress((void**)&counters, g_counters);

    init_kernel<<<64, 256>>>(counters, hping);

    // pre0[t][j][b] = inputs[b][t][:] . W_ih0[j][:] + b_ih0[j] + b_hh0[j]
    gemm_pre_kernel<<<dim3(4, TT), 128>>>(inputs, W_ih0, b_ih0, b_hh0, pre,
                                          II, (long)II, 1L, (long)TT * II, HH);

    // layer 0 recurrence -> h1 trajectory
    rnn_layer_kernel<<<128, 256>>>(pre, traj, W_hh0,
                                   hping, hping + HH * BB, counters);

    // pre1[t][j][b] = h1[t][:][b] . W_ih1[j][:] + b_ih1[j] + b_hh1[j]
    gemm_pre_kernel<<<dim3(4, TT), 128>>>(traj, W_ih1, b_ih1, b_hh1, pre,
                                          HH, (long)HH * BB, (long)BB, 1L, HH);

    // layer 1 recurrence -> h2 trajectory (reuses g_traj)
    rnn_layer_kernel<<<128, 256>>>(pre, traj, W_hh1,
                                   hping + 2 * HH * BB, hping + 3 * HH * BB,
                                   counters + 512);

    // fc: tmp[t][o][b] = h2[t][:][b] . W_fc[o][:] + b_fc[o]
    gemm_pre_kernel<<<dim3(1, TT), 128>>>(traj, W_fc, b_fc, nullptr, tmp,
                                          HH, (long)HH * BB, (long)BB, 1L, OO);

    // out[b][o][t] = tmp[t][o][b]
    transpose_kernel<<<dim3(16, OO), dim3(32, 8)>>>(tmp, (float*)d_out);
}

// round 4
// speedup vs baseline: 1.0722x; 1.0699x over previous
#include <cuda_runtime.h>
#include <math.h>
#include <stdint.h>

// Problem dims
#define BB 32
#define TT 512
#define II 128
#define HH 512
#define OO 128

// ---------------- device scratch (no allocs allowed) ----------------
__device__ float    g_pre [TT * HH * BB];   // [T][H][B] (reused pre0/pre1)
__device__ float    g_traj[TT * HH * BB];   // [T][H][B] (h1, then reused as h2)
__device__ float    g_tmp [TT * OO * BB];   // [T][O][B] (fc pre-transpose)
__device__ float    g_hping[4 * HH * BB];   // 2 ping-pong pairs (layer0, layer1)
__device__ unsigned g_counters[1024];       // per-step barrier counters (512 per layer)

// ---------------- init: zero counters + h0 buffers each replay ----------------
__global__ void init_kernel(unsigned* counters, float* hping) {
    int i = blockIdx.x * blockDim.x + threadIdx.x;
    int stride = gridDim.x * blockDim.x;
    for (int e = i; e < 1024; e += stride) counters[e] = 0u;
    for (int e = i; e < 4 * HH * BB; e += stride) hping[e] = 0.0f;
}

// ---------------- fp32 GEMM: C[t][j][b] = bias(j) + sum_k A(t,k,b)*W[j][k] ----------------
// grid: (N/128, T/2), block: 256. Tile 128j x 64n (n = 2 timesteps x 32 b),
// microtile 8j x 4n. Coalesced staging for both A layouts.
__global__ void __launch_bounds__(256)
gemm_pre_kernel(const float* __restrict__ A, const float* __restrict__ W,
                const float* __restrict__ bias1, const float* __restrict__ bias2,
                float* __restrict__ C,
                int K, long sAt, long sAk, long sAb, int N)
{
    __shared__ float Ws[32][132];  // [k][j] padded (128 j)
    __shared__ float As[32][68];   // [k][n] padded (64 n)

    const int t0  = blockIdx.y * 2;
    const int j0  = blockIdx.x * 128;
    const int tid = threadIdx.x;
    const int jg  = tid >> 4;      // 0..15 (8 j each)
    const int ng  = tid & 15;      // 0..15 (4 n each)

    float acc[8][4];
#pragma unroll
    for (int a = 0; a < 8; a++)
#pragma unroll
        for (int b = 0; b < 4; b++) acc[a][b] = 0.0f;

    for (int kt = 0; kt < K; kt += 32) {
        __syncthreads();
        // --- stage W tile transposed, coalesced: 8 threads cover one row's 32 k ---
        {
            const int rowb = tid >> 3;        // 0..31
            const int k4   = (tid & 7) * 4;   // 0,4,..,28
#pragma unroll
            for (int i = 0; i < 4; i++) {
                const int row = i * 32 + rowb;
                float4 v = *(const float4*)&W[(size_t)(j0 + row) * K + kt + k4];
                Ws[k4 + 0][row] = v.x;
                Ws[k4 + 1][row] = v.y;
                Ws[k4 + 2][row] = v.z;
                Ws[k4 + 3][row] = v.w;
            }
        }
        // --- stage A tile: 32 k x 64 n ---
        if (sAb == 1) {   // b-contiguous (trajectory layout [t][k][b])
#pragma unroll
            for (int i = 0; i < 2; i++) {
                int f = tid + i * 256;
                int k  = f >> 4;             // 0..31
                int nq = (f & 15) * 4;       // 0..60
                int tloc = nq >> 5, b4 = nq & 31;
                float4 v = *(const float4*)&A[(size_t)(t0 + tloc) * sAt +
                                              (size_t)(kt + k) * sAk + b4];
                *(float4*)&As[k][nq] = v;
            }
        } else {          // k-contiguous (inputs layout [b][t][i])
#pragma unroll
            for (int i = 0; i < 2; i++) {
                int f = tid + i * 256;
                int n  = f >> 3;             // 0..63
                int kq = (f & 7) * 4;        // 0..28
                int tloc = n >> 5, b = n & 31;
                float4 v = *(const float4*)&A[(size_t)b * sAb +
                                              (size_t)(t0 + tloc) * sAt + kt + kq];
                As[kq + 0][n] = v.x;
                As[kq + 1][n] = v.y;
                As[kq + 2][n] = v.z;
                As[kq + 3][n] = v.w;
            }
        }
        __syncthreads();
#pragma unroll
        for (int k = 0; k < 32; k++) {
            const float4 w0 = *(const float4*)&Ws[k][jg * 8];
            const float4 w1 = *(const float4*)&Ws[k][jg * 8 + 4];
            const float4 a  = *(const float4*)&As[k][ng * 4];
            acc[0][0] += w0.x * a.x; acc[0][1] += w0.x * a.y; acc[0][2] += w0.x * a.z; acc[0][3] += w0.x * a.w;
            acc[1][0] += w0.y * a.x; acc[1][1] += w0.y * a.y; acc[1][2] += w0.y * a.z; acc[1][3] += w0.y * a.w;
            acc[2][0] += w0.z * a.x; acc[2][1] += w0.z * a.y; acc[2][2] += w0.z * a.z; acc[2][3] += w0.z * a.w;
            acc[3][0] += w0.w * a.x; acc[3][1] += w0.w * a.y; acc[3][2] += w0.w * a.z; acc[3][3] += w0.w * a.w;
            acc[4][0] += w1.x * a.x; acc[4][1] += w1.x * a.y; acc[4][2] += w1.x * a.z; acc[4][3] += w1.x * a.w;
            acc[5][0] += w1.y * a.x; acc[5][1] += w1.y * a.y; acc[5][2] += w1.y * a.z; acc[5][3] += w1.y * a.w;
            acc[6][0] += w1.z * a.x; acc[6][1] += w1.z * a.y; acc[6][2] += w1.z * a.z; acc[6][3] += w1.z * a.w;
            acc[7][0] += w1.w * a.x; acc[7][1] += w1.w * a.y; acc[7][2] += w1.w * a.z; acc[7][3] += w1.w * a.w;
        }
    }

    // epilogue: this thread's 4 n are within one timestep
    const int tloc = ng >> 3;
    const int b4   = (ng & 7) * 4;
    float* Crow = &C[(size_t)(t0 + tloc) * N * BB + b4];
#pragma unroll
    for (int ji = 0; ji < 8; ji++) {
        int j = j0 + jg * 8 + ji;
        float bb = bias1 ? bias1[j] : 0.0f;
        if (bias2) bb += bias2[j];
        float4 o = make_float4(acc[ji][0] + bb, acc[ji][1] + bb, acc[ji][2] + bb, acc[ji][3] + bb);
        *(float4*)&Crow[(size_t)j * BB] = o;
    }
}

// ---------------- persistent recurrence layer (R1-proven structure) ----------------
// grid: 128 CTAs (co-resident), block: 128 threads. CTA owns 4 hidden columns.
// h buffers [H][B]. Grid barrier: bar.sync -> tid0 red.release + acquire spin w/ nanosleep.
__global__ void __launch_bounds__(128)
rnn_layer_kernel(const float* __restrict__ pre, float* __restrict__ traj,
                 const float* __restrict__ W,
                 float* buf0, float* buf1, unsigned* counters)
{
    __shared__ float Wt[16][32][4];   // [kk][kseg][jj]  8KB
    __shared__ float ps[32][132];     // partials [kseg][out], padded

    const int tid  = threadIdx.x;
    const int j0   = blockIdx.x * 4;
    const int bg   = tid & 3;
    const int kseg = tid >> 2;        // 0..31
    const int b0   = bg * 8;

    // preload W slice: Wt[kk][ks][jj] = W[(j0+jj)*H + ks*16 + kk]
    for (int e = tid; e < 2048; e += 128) {
        int jj = e & 3;
        int ks = (e >> 2) & 31;
        int kk = e >> 7;
        Wt[kk][ks][jj] = W[(size_t)(j0 + jj) * HH + ks * 16 + kk];
    }
    __syncthreads();

    const int out_b  = tid >> 2;      // output this thread finalizes
    const int out_jj = tid & 3;

    for (int t = 0; t < TT; t++) {
        const float* hb = (t & 1) ? buf1 : buf0;
        float*       hn = (t & 1) ? buf0 : buf1;

        // prefetch pre-activation for this thread's output
        const float preval = pre[(size_t)t * (HH * BB) + (size_t)(j0 + out_jj) * BB + out_b];

        float acc[8][4];
#pragma unroll
        for (int a = 0; a < 8; a++)
#pragma unroll
            for (int b = 0; b < 4; b++) acc[a][b] = 0.0f;

#pragma unroll
        for (int kk = 0; kk < 16; kk++) {
            const int k = kseg * 16 + kk;
            const float4 w  = *(const float4*)&Wt[kk][kseg][0];
            const float4 hA = __ldcg((const float4*)(hb + (k << 5) + b0));
            const float4 hB = __ldcg((const float4*)(hb + (k << 5) + b0 + 4));
            acc[0][0] += hA.x * w.x; acc[0][1] += hA.x * w.y; acc[0][2] += hA.x * w.z; acc[0][3] += hA.x * w.w;
            acc[1][0] += hA.y * w.x; acc[1][1] += hA.y * w.y; acc[1][2] += hA.y * w.z; acc[1][3] += hA.y * w.w;
            acc[2][0] += hA.z * w.x; acc[2][1] += hA.z * w.y; acc[2][2] += hA.z * w.z; acc[2][3] += hA.z * w.w;
            acc[3][0] += hA.w * w.x; acc[3][1] += hA.w * w.y; acc[3][2] += hA.w * w.z; acc[3][3] += hA.w * w.w;
            acc[4][0] += hB.x * w.x; acc[4][1] += hB.x * w.y; acc[4][2] += hB.x * w.z; acc[4][3] += hB.x * w.w;
            acc[5][0] += hB.y * w.x; acc[5][1] += hB.y * w.y; acc[5][2] += hB.y * w.z; acc[5][3] += hB.y * w.w;
            acc[6][0] += hB.z * w.x; acc[6][1] += hB.z * w.y; acc[6][2] += hB.z * w.z; acc[6][3] += hB.z * w.w;
            acc[7][0] += hB.w * w.x; acc[7][1] += hB.w * w.y; acc[7][2] += hB.w * w.z; acc[7][3] += hB.w * w.w;
        }

        // dump partials: out index = b*4 + jj
#pragma unroll
        for (int bi = 0; bi < 8; bi++) {
            *(float4*)&ps[kseg][(bg * 8 + bi) * 4] =
                make_float4(acc[bi][0], acc[bi][1], acc[bi][2], acc[bi][3]);
        }
        __syncthreads();

        // reduce 32 k-segments for output 'tid'
        float s0 = 0.f, s1 = 0.f, s2 = 0.f, s3 = 0.f;
#pragma unroll
        for (int ss = 0; ss < 32; ss += 4) {
            s0 += ps[ss + 0][tid];
            s1 += ps[ss + 1][tid];
            s2 += ps[ss + 2][tid];
            s3 += ps[ss + 3][tid];
        }
        const float val = tanhf(preval + (s0 + s1) + (s2 + s3));
        const int jdx = j0 + out_jj;
        hn[(size_t)jdx * BB + out_b] = val;
        traj[(size_t)t * (HH * BB) + (size_t)jdx * BB + out_b] = val;

        __syncthreads();   // all h stores ordered before tid0's release; guards ps reuse

        if (tid == 0) {
            unsigned* cnt = &counters[t];
            asm volatile("red.release.gpu.global.add.u32 [%0], 1;" :: "l"(cnt) : "memory");
            unsigned v;
            do {
                asm volatile("ld.acquire.gpu.global.u32 %0, [%1];" : "=r"(v) : "l"(cnt) : "memory");
                if (v >= 128u) break;
                __nanosleep(40);
            } while (true);
        }
        __syncthreads();
    }
}

// ---------------- transpose: g_tmp [T][O][B] -> out [B][O][T] ----------------
__global__ void transpose_kernel(const float* __restrict__ tmp, float* __restrict__ out)
{
    __shared__ float s[32][33];
    const int t0 = blockIdx.x * 32;
    const int o  = blockIdx.y;
    const int tx = threadIdx.x;   // 32
    const int ty = threadIdx.y;   // 8
#pragma unroll
    for (int i = 0; i < 4; i++) {
        int tt = t0 + ty + i * 8;
        s[ty + i * 8][tx] = tmp[(size_t)tt * (OO * BB) + (size_t)o * BB + tx];
    }
    __syncthreads();
#pragma unroll
    for (int i = 0; i < 4; i++) {
        int b = ty + i * 8;
        out[(size_t)b * (OO * TT) + (size_t)o * TT + t0 + tx] = s[tx][b];
    }
}

// ---------------- launch ----------------
extern "C" void kernel_launch(void* const* d_in, const int* in_sizes, int n_in,
                              void* d_out, int out_size)
{
    const float* inputs = (const float*)d_in[0];
    const float* W_ih0  = (const float*)d_in[1];
    const float* W_hh0  = (const float*)d_in[2];
    const float* b_ih0  = (const float*)d_in[3];
    const float* b_hh0  = (const float*)d_in[4];
    const float* W_ih1  = (const float*)d_in[5];
    const float* W_hh1  = (const float*)d_in[6];
    const float* b_ih1  = (const float*)d_in[7];
    const float* b_hh1  = (const float*)d_in[8];
    const float* W_fc   = (const float*)d_in[9];
    const float* b_fc   = (const float*)d_in[10];

    float *pre, *traj, *tmp, *hping;
    unsigned* counters;
    cudaGetSymbolAddress((void**)&pre,      g_pre);
    cudaGetSymbolAddress((void**)&traj,     g_traj);
    cudaGetSymbolAddress((void**)&tmp,      g_tmp);
    cudaGetSymbolAddress((void**)&hping,    g_hping);
    cudaGetSymbolAddress((void**)&counters, g_counters);

    init_kernel<<<64, 256>>>(counters, hping);

    // pre0[t][j][b] = inputs[b][t][:] . W_ih0[j][:] + b_ih0[j] + b_hh0[j]
    gemm_pre_kernel<<<dim3(4, TT / 2), 256>>>(inputs, W_ih0, b_ih0, b_hh0, pre,
                                              II, (long)II, 1L, (long)TT * II, HH);

    // layer 0 recurrence -> h1 trajectory
    rnn_layer_kernel<<<128, 128>>>(pre, traj, W_hh0,
                                   hping, hping + HH * BB, counters);

    // pre1[t][j][b] = h1[t][:][b] . W_ih1[j][:] + b_ih1[j] + b_hh1[j]
    gemm_pre_kernel<<<dim3(4, TT / 2), 256>>>(traj, W_ih1, b_ih1, b_hh1, pre,
                                              HH, (long)HH * BB, (long)BB, 1L, HH);

    // layer 1 recurrence -> h2 trajectory (reuses g_traj)
    rnn_layer_kernel<<<128, 128>>>(pre, traj, W_hh1,
                                   hping + 2 * HH * BB, hping + 3 * HH * BB,
                                   counters + 512);

    // fc: tmp[t][o][b] = h2[t][:][b] . W_fc[o][:] + b_fc[o]
    gemm_pre_kernel<<<dim3(1, TT / 2), 256>>>(traj, W_fc, b_fc, nullptr, tmp,
                                              HH, (long)HH * BB, (long)BB, 1L, OO);

    // out[b][o][t] = tmp[t][o][b]
    transpose_kernel<<<dim3(16, OO), dim3(32, 8)>>>(tmp, (float*)d_out);
}

// round 6
// speedup vs baseline: 1.3865x; 1.2932x over previous
#include <cuda_runtime.h>
#include <math.h>
#include <stdint.h>

// Problem dims
#define BB 32
#define TT 512
#define II 128
#define HH 512
#define OO 128

// ---------------- device scratch (no allocs allowed) ----------------
__device__ float    g_pre [TT * HH * BB];   // [T][H][B] (reused pre0/pre1)
__device__ float    g_traj[TT * HH * BB];   // [T][H][B] (h1, then reused as h2)
__device__ float    g_tmp [TT * OO * BB];   // [T][O][B] (fc pre-transpose)
__device__ float    g_hping[4 * HH * BB];   // 2 ping-pong pairs (layer0, layer1)
__device__ unsigned g_counters[1024];       // per-step barrier counters (512 per layer)

// ---------------- init: zero counters + h0 buffers each replay ----------------
__global__ void init_kernel(unsigned* counters, float* hping) {
    int i = blockIdx.x * blockDim.x + threadIdx.x;
    int stride = gridDim.x * blockDim.x;
    for (int e = i; e < 1024; e += stride) counters[e] = 0u;
    for (int e = i; e < 4 * HH * BB; e += stride) hping[e] = 0.0f;
}

// ---------------- fp32 GEMM: C[t][j][b] = bias(j) + sum_k A(t,k,b)*W[j][k] ----------------
// grid: (N/128, T/2), block: 256. Tile 128j x 64n (n = 2 timesteps x 32 b),
// microtile 8j x 4n. Coalesced staging for both A layouts.  (R4 version — keep)
__global__ void __launch_bounds__(256)
gemm_pre_kernel(const float* __restrict__ A, const float* __restrict__ W,
                const float* __restrict__ bias1, const float* __restrict__ bias2,
                float* __restrict__ C,
                int K, long sAt, long sAk, long sAb, int N)
{
    __shared__ float Ws[32][132];  // [k][j] padded (128 j)
    __shared__ float As[32][68];   // [k][n] padded (64 n)

    const int t0  = blockIdx.y * 2;
    const int j0  = blockIdx.x * 128;
    const int tid = threadIdx.x;
    const int jg  = tid >> 4;      // 0..15 (8 j each)
    const int ng  = tid & 15;      // 0..15 (4 n each)

    float acc[8][4];
#pragma unroll
    for (int a = 0; a < 8; a++)
#pragma unroll
        for (int b = 0; b < 4; b++) acc[a][b] = 0.0f;

    for (int kt = 0; kt < K; kt += 32) {
        __syncthreads();
        // --- stage W tile transposed, coalesced: 8 threads cover one row's 32 k ---
        {
            const int rowb = tid >> 3;        // 0..31
            const int k4   = (tid & 7) * 4;   // 0,4,..,28
#pragma unroll
            for (int i = 0; i < 4; i++) {
                const int row = i * 32 + rowb;
                float4 v = *(const float4*)&W[(size_t)(j0 + row) * K + kt + k4];
                Ws[k4 + 0][row] = v.x;
                Ws[k4 + 1][row] = v.y;
                Ws[k4 + 2][row] = v.z;
                Ws[k4 + 3][row] = v.w;
            }
        }
        // --- stage A tile: 32 k x 64 n ---
        if (sAb == 1) {   // b-contiguous (trajectory layout [t][k][b])
#pragma unroll
            for (int i = 0; i < 2; i++) {
                int f = tid + i * 256;
                int k  = f >> 4;             // 0..31
                int nq = (f & 15) * 4;       // 0..60
                int tloc = nq >> 5, b4 = nq & 31;
                float4 v = *(const float4*)&A[(size_t)(t0 + tloc) * sAt +
                                              (size_t)(kt + k) * sAk + b4];
                *(float4*)&As[k][nq] = v;
            }
        } else {          // k-contiguous (inputs layout [b][t][i])
#pragma unroll
            for (int i = 0; i < 2; i++) {
                int f = tid + i * 256;
                int n  = f >> 3;             // 0..63
                int kq = (f & 7) * 4;        // 0..28
                int tloc = n >> 5, b = n & 31;
                float4 v = *(const float4*)&A[(size_t)b * sAb +
                                              (size_t)(t0 + tloc) * sAt + kt + kq];
                As[kq + 0][n] = v.x;
                As[kq + 1][n] = v.y;
                As[kq + 2][n] = v.z;
                As[kq + 3][n] = v.w;
            }
        }
        __syncthreads();
#pragma unroll
        for (int k = 0; k < 32; k++) {
            const float4 w0 = *(const float4*)&Ws[k][jg * 8];
            const float4 w1 = *(const float4*)&Ws[k][jg * 8 + 4];
            const float4 a  = *(const float4*)&As[k][ng * 4];
            acc[0][0] += w0.x * a.x; acc[0][1] += w0.x * a.y; acc[0][2] += w0.x * a.z; acc[0][3] += w0.x * a.w;
            acc[1][0] += w0.y * a.x; acc[1][1] += w0.y * a.y; acc[1][2] += w0.y * a.z; acc[1][3] += w0.y * a.w;
            acc[2][0] += w0.z * a.x; acc[2][1] += w0.z * a.y; acc[2][2] += w0.z * a.z; acc[2][3] += w0.z * a.w;
            acc[3][0] += w0.w * a.x; acc[3][1] += w0.w * a.y; acc[3][2] += w0.w * a.z; acc[3][3] += w0.w * a.w;
            acc[4][0] += w1.x * a.x; acc[4][1] += w1.x * a.y; acc[4][2] += w1.x * a.z; acc[4][3] += w1.x * a.w;
            acc[5][0] += w1.y * a.x; acc[5][1] += w1.y * a.y; acc[5][2] += w1.y * a.z; acc[5][3] += w1.y * a.w;
            acc[6][0] += w1.z * a.x; acc[6][1] += w1.z * a.y; acc[6][2] += w1.z * a.z; acc[6][3] += w1.z * a.w;
            acc[7][0] += w1.w * a.x; acc[7][1] += w1.w * a.y; acc[7][2] += w1.w * a.z; acc[7][3] += w1.w * a.w;
        }
    }

    // epilogue: this thread's 4 n are within one timestep
    const int tloc = ng >> 3;
    const int b4   = (ng & 7) * 4;
    float* Crow = &C[(size_t)(t0 + tloc) * N * BB + b4];
#pragma unroll
    for (int ji = 0; ji < 8; ji++) {
        int j = j0 + jg * 8 + ji;
        float bb = bias1 ? bias1[j] : 0.0f;
        if (bias2) bb += bias2[j];
        float4 o = make_float4(acc[ji][0] + bb, acc[ji][1] + bb, acc[ji][2] + bb, acc[ji][3] + bb);
        *(float4*)&Crow[(size_t)j * BB] = o;
    }
}

// ---------------- persistent recurrence layer ----------------
// grid: 128 CTAs (co-resident), block: 128 threads. CTA owns 4 hidden columns.
// h buffers [H][B]. Grid barrier: R1-proven threadfence + atomicAdd-return +
// volatile spin with nanosleep backoff.
__global__ void __launch_bounds__(128)
rnn_layer_kernel(const float* __restrict__ pre, float* __restrict__ traj,
                 const float* __restrict__ W,
                 float* buf0, float* buf1, unsigned* counters)
{
    __shared__ float Wt[16][32][4];   // [kk][kseg][jj]  8KB
    __shared__ float ps[32][132];     // partials [kseg][out], padded

    const int tid  = threadIdx.x;
    const int j0   = blockIdx.x * 4;
    const int bg   = tid & 3;
    const int kseg = tid >> 2;        // 0..31
    const int b0   = bg * 8;

    // preload W slice: Wt[kk][ks][jj] = W[(j0+jj)*H + ks*16 + kk]
    for (int e = tid; e < 2048; e += 128) {
        int jj = e & 3;
        int ks = (e >> 2) & 31;
        int kk = e >> 7;
        Wt[kk][ks][jj] = W[(size_t)(j0 + jj) * HH + ks * 16 + kk];
    }
    __syncthreads();

    const int out_b  = tid >> 2;      // output this thread finalizes
    const int out_jj = tid & 3;

    for (int t = 0; t < TT; t++) {
        const float* hb = (t & 1) ? buf1 : buf0;
        float*       hn = (t & 1) ? buf0 : buf1;

        // prefetch pre-activation for this thread's output
        const float preval = pre[(size_t)t * (HH * BB) + (size_t)(j0 + out_jj) * BB + out_b];

        float acc[8][4];
#pragma unroll
        for (int a = 0; a < 8; a++)
#pragma unroll
            for (int b = 0; b < 4; b++) acc[a][b] = 0.0f;

#pragma unroll
        for (int kk = 0; kk < 16; kk++) {
            const int k = kseg * 16 + kk;
            const float4 w  = *(const float4*)&Wt[kk][kseg][0];
            const float4 hA = __ldcg((const float4*)(hb + (k << 5) + b0));
            const float4 hB = __ldcg((const float4*)(hb + (k << 5) + b0 + 4));
            acc[0][0] += hA.x * w.x; acc[0][1] += hA.x * w.y; acc[0][2] += hA.x * w.z; acc[0][3] += hA.x * w.w;
            acc[1][0] += hA.y * w.x; acc[1][1] += hA.y * w.y; acc[1][2] += hA.y * w.z; acc[1][3] += hA.y * w.w;
            acc[2][0] += hA.z * w.x; acc[2][1] += hA.z * w.y; acc[2][2] += hA.z * w.z; acc[2][3] += hA.z * w.w;
            acc[3][0] += hA.w * w.x; acc[3][1] += hA.w * w.y; acc[3][2] += hA.w * w.z; acc[3][3] += hA.w * w.w;
            acc[4][0] += hB.x * w.x; acc[4][1] += hB.x * w.y; acc[4][2] += hB.x * w.z; acc[4][3] += hB.x * w.w;
            acc[5][0] += hB.y * w.x; acc[5][1] += hB.y * w.y; acc[5][2] += hB.y * w.z; acc[5][3] += hB.y * w.w;
            acc[6][0] += hB.z * w.x; acc[6][1] += hB.z * w.y; acc[6][2] += hB.z * w.z; acc[6][3] += hB.z * w.w;
            acc[7][0] += hB.w * w.x; acc[7][1] += hB.w * w.y; acc[7][2] += hB.w * w.z; acc[7][3] += hB.w * w.w;
        }

        // dump partials: out index = b*4 + jj
#pragma unroll
        for (int bi = 0; bi < 8; bi++) {
            *(float4*)&ps[kseg][(bg * 8 + bi) * 4] =
                make_float4(acc[bi][0], acc[bi][1], acc[bi][2], acc[bi][3]);
        }
        __syncthreads();

        // reduce 32 k-segments for output 'tid' (4-way split chains)
        float s0 = 0.f, s1 = 0.f, s2 = 0.f, s3 = 0.f;
#pragma unroll
        for (int ss = 0; ss < 32; ss += 4) {
            s0 += ps[ss + 0][tid];
            s1 += ps[ss + 1][tid];
            s2 += ps[ss + 2][tid];
            s3 += ps[ss + 3][tid];
        }
        const float val = tanhf(preval + (s0 + s1) + (s2 + s3));
        const int jdx = j0 + out_jj;
        hn[(size_t)jdx * BB + out_b] = val;
        traj[(size_t)t * (HH * BB) + (size_t)jdx * BB + out_b] = val;

        __threadfence();
        __syncthreads();   // all stores + fences done; also guards ps reuse

        if (tid == 0) {
            unsigned arrived = atomicAdd(&counters[t], 1u) + 1u;
            if (arrived < 128u) {
                volatile unsigned* p = &counters[t];
                while (*p < 128u) { __nanosleep(40); }
            }
        }
        __syncthreads();
    }
}

// ---------------- transpose: g_tmp [T][O][B] -> out [B][O][T] ----------------
__global__ void transpose_kernel(const float* __restrict__ tmp, float* __restrict__ out)
{
    __shared__ float s[32][33];
    const int t0 = blockIdx.x * 32;
    const int o  = blockIdx.y;
    const int tx = threadIdx.x;   // 32
    const int ty = threadIdx.y;   // 8
#pragma unroll
    for (int i = 0; i < 4; i++) {
        int tt = t0 + ty + i * 8;
        s[ty + i * 8][tx] = tmp[(size_t)tt * (OO * BB) + (size_t)o * BB + tx];
    }
    __syncthreads();
#pragma unroll
    for (int i = 0; i < 4; i++) {
        int b = ty + i * 8;
        out[(size_t)b * (OO * TT) + (size_t)o * TT + t0 + tx] = s[tx][b];
    }
}

// ---------------- launch ----------------
extern "C" void kernel_launch(void* const* d_in, const int* in_sizes, int n_in,
                              void* d_out, int out_size)
{
    const float* inputs = (const float*)d_in[0];
    const float* W_ih0  = (const float*)d_in[1];
    const float* W_hh0  = (const float*)d_in[2];
    const float* b_ih0  = (const float*)d_in[3];
    const float* b_hh0  = (const float*)d_in[4];
    const float* W_ih1  = (const float*)d_in[5];
    const float* W_hh1  = (const float*)d_in[6];
    const float* b_ih1  = (const float*)d_in[7];
    const float* b_hh1  = (const float*)d_in[8];
    const float* W_fc   = (const float*)d_in[9];
    const float* b_fc   = (const float*)d_in[10];

    float *pre, *traj, *tmp, *hping;
    unsigned* counters;
    cudaGetSymbolAddress((void**)&pre,      g_pre);
    cudaGetSymbolAddress((void**)&traj,     g_traj);
    cudaGetSymbolAddress((void**)&tmp,      g_tmp);
    cudaGetSymbolAddress((void**)&hping,    g_hping);
    cudaGetSymbolAddress((void**)&counters, g_counters);

    init_kernel<<<64, 256>>>(counters, hping);

    // pre0[t][j][b] = inputs[b][t][:] . W_ih0[j][:] + b_ih0[j] + b_hh0[j]
    gemm_pre_kernel<<<dim3(4, TT / 2), 256>>>(inputs, W_ih0, b_ih0, b_hh0, pre,
                                              II, (long)II, 1L, (long)TT * II, HH);

    // layer 0 recurrence -> h1 trajectory
    rnn_layer_kernel<<<128, 128>>>(pre, traj, W_hh0,
                                   hping, hping + HH * BB, counters);

    // pre1[t][j][b] = h1[t][:][b] . W_ih1[j][:] + b_ih1[j] + b_hh1[j]
    gemm_pre_kernel<<<dim3(4, TT / 2), 256>>>(traj, W_ih1, b_ih1, b_hh1, pre,
                                              HH, (long)HH * BB, (long)BB, 1L, HH);

    // layer 1 recurrence -> h2 trajectory (reuses g_traj)
    rnn_layer_kernel<<<128, 128>>>(pre, traj, W_hh1,
                                   hping + 2 * HH * BB, hping + 3 * HH * BB,
                                   counters + 512);

    // fc: tmp[t][o][b] = h2[t][:][b] . W_fc[o][:] + b_fc[o]
    gemm_pre_kernel<<<dim3(1, TT / 2), 256>>>(traj, W_fc, b_fc, nullptr, tmp,
                                              HH, (long)HH * BB, (long)BB, 1L, OO);

    // out[b][o][t] = tmp[t][o][b]
    transpose_kernel<<<dim3(16, OO), dim3(32, 8)>>>(tmp, (float*)d_out);
}